// round 5
// baseline (speedup 1.0000x reference)
#include <cuda_runtime.h>
#include <cuda_bf16.h>
#include <cstdint>

// YOLOv7 P3 head: B=16, A=3, NC=80, H=W=80, stride=8.
// in : [B, A*85, H, W] fp32 (channel-major)
// out: [B, A*H*W, 85] fp32 (85 contiguous per location)

#define YB 16
#define YA 3
#define YC 85
#define YH 80
#define YW 80
#define YHW (YH * YW)        // 6400
#define LOCS 64              // spatial locations per tile
#define NCHUNK (YHW / LOCS)  // 100 tiles per (b,a)
#define THREADS 256
#define NWARP (THREADS / 32)

#define CGROUPS 22                   // ceil(85/4)
#define IBLOCKS (LOCS / 32)          // 2
#define NTASKS (CGROUPS * IBLOCKS)   // 44 warp-tasks per tile
#define TPT ((NTASKS + NWARP - 1) / NWARP)  // 6 tasks per thread

#define TILE_BYTES (LOCS * YC * 4)   // 21760
#define TILES_PER_CTA 2
#define NTILES (YB * YA * NCHUNK)    // 4800

__device__ __forceinline__ float fast_sigmoid(float x) {
    // sigmoid(x) = 0.5*tanh(0.5x) + 0.5  -> single MUFU.TANH + FMA
    float t;
    asm("tanh.approx.f32 %0, %1;" : "=f"(t) : "f"(0.5f * x));
    return fmaf(0.5f, t, 0.5f);
}

__global__ __launch_bounds__(THREADS)
void yolov7_head_kernel(const float* __restrict__ in,
                        const float* __restrict__ anchors,
                        float* __restrict__ out) {
    // double-buffered, output-linear: so[buf][loc*85 + c]
    __shared__ __align__(16) float so[TILES_PER_CTA][LOCS * YC];  // 43520 B

    const int tid  = threadIdx.x;
    const int warp = tid >> 5;
    const int lane = tid & 31;
    const int q    = lane >> 3;   // channel within quad (0..3)
    const int l8   = lane & 7;    // float4 within 8-block

    const int tile0 = blockIdx.x * TILES_PER_CTA;

    #pragma unroll
    for (int it = 0; it < TILES_PER_CTA; it++) {
        const int tile  = tile0 + it;
        const int chunk = tile % NCHUNK;
        const int ba    = tile / NCHUNK;      // b*A + a
        const int a     = ba % YA;
        const int hw0   = chunk * LOCS;

        const float aw = anchors[a * 2 + 0];
        const float ah = anchors[a * 2 + 1];

        const float4* in4 = reinterpret_cast<const float4*>(
            in + (size_t)ba * YC * YHW + hw0);
        float* sob = so[it];

        // ---- front-batched loads: all 6 LDG.128 issued before any use ----
        float4 v[TPT];
        #pragma unroll
        for (int t = 0; t < TPT; t++) {
            const int task = warp + NWARP * t;
            const int c    = (task >> 1) * 4 + q;
            const int i4   = (task & 1) * 8 + l8;
            if (task < NTASKS && c < YC)
                v[t] = in4[c * (YHW / 4) + i4];
        }

        // ---- transform + conflict-free STS (output-linear scatter) ----
        #pragma unroll
        for (int t = 0; t < TPT; t++) {
            const int task = warp + NWARP * t;
            const int c    = (task >> 1) * 4 + q;
            const int i4   = (task & 1) * 8 + l8;
            if (task < NTASKS && c < YC) {
                const float vals[4] = {v[t].x, v[t].y, v[t].z, v[t].w};
                const int loc0 = i4 * 4;
                if (c >= 4) {
                    #pragma unroll
                    for (int k = 0; k < 4; k++)
                        sob[(loc0 + k) * YC + c] = fast_sigmoid(vals[k]);
                } else if (c == 0) {
                    #pragma unroll
                    for (int k = 0; k < 4; k++) {
                        const int hw = hw0 + loc0 + k;
                        const float gx = (float)(hw % YW);
                        sob[(loc0 + k) * YC + c] = (fast_sigmoid(vals[k]) + gx) * 8.0f;
                    }
                } else if (c == 1) {
                    #pragma unroll
                    for (int k = 0; k < 4; k++) {
                        const int hw = hw0 + loc0 + k;
                        const float gy = (float)(hw / YW);
                        sob[(loc0 + k) * YC + c] = (fast_sigmoid(vals[k]) + gy) * 8.0f;
                    }
                } else {  // c == 2 or 3
                    const float anc = (c == 2) ? aw : ah;
                    #pragma unroll
                    for (int k = 0; k < 4; k++) {
                        float x = fminf(fmaxf(vals[k], -16.0f), 16.0f);
                        sob[(loc0 + k) * YC + c] = __expf(x) * anc;
                    }
                }
            }
        }

        __syncthreads();

        // ---- commit async bulk store; do NOT wait (drains during next tile) ----
        if (tid == 0) {
            float* gdst = out + ((size_t)ba * YHW + hw0) * YC;
            uint32_t saddr;
            asm("{ .reg .u64 t; cvta.to.shared.u64 t, %1; cvt.u32.u64 %0, t; }"
                : "=r"(saddr) : "l"(sob));
            asm volatile("fence.proxy.async.shared::cta;" ::: "memory");
            asm volatile(
                "cp.async.bulk.global.shared::cta.bulk_group [%0], [%1], %2;"
                :: "l"(gdst), "r"(saddr), "n"(TILE_BYTES) : "memory");
            asm volatile("cp.async.bulk.commit_group;" ::: "memory");
        }
        // next iteration writes the OTHER buffer -> no wait needed here
    }

    // keep CTA (and its smem) alive until the bulk engine has read both buffers
    if (tid == 0)
        asm volatile("cp.async.bulk.wait_group.read 0;" ::: "memory");
}

extern "C" void kernel_launch(void* const* d_in, const int* in_sizes, int n_in,
                              void* d_out, int out_size) {
    const float* in      = (const float*)d_in[0];
    const float* anchors = (const float*)d_in[1];
    float* out           = (float*)d_out;

    const int grid = NTILES / TILES_PER_CTA;  // 2400
    yolov7_head_kernel<<<grid, THREADS>>>(in, anchors, out);
}

// round 8
// speedup vs baseline: 1.2393x; 1.2393x over previous
#include <cuda_runtime.h>
#include <cuda_bf16.h>
#include <cstdint>

// YOLOv7 P3 head: B=16, A=3, NC=80, H=W=80, stride=8.
// in : [B, A*85, H, W] fp32 (channel-major)
// out: [B, A*H*W, 85] fp32 (85 contiguous per location)

#define YB 16
#define YA 3
#define YC 85
#define YH 80
#define YW 80
#define YHW (YH * YW)        // 6400
#define LOCS 64              // spatial locations per tile
#define NCHUNK (YHW / LOCS)  // 100 tiles per (b,a)
#define THREADS 256
#define NWARP (THREADS / 32)

#define CGROUPS 22                   // ceil(85/4)
#define IBLOCKS (LOCS / 32)          // 2
#define NTASKS (CGROUPS * IBLOCKS)   // 44 warp-tasks per tile
#define TPT ((NTASKS + NWARP - 1) / NWARP)  // 6 tasks per thread

#define TILE_BYTES (LOCS * YC * 4)   // 21760

__device__ __forceinline__ float fast_sigmoid(float x) {
    // sigmoid(x) = 0.5*tanh(0.5x) + 0.5  -> single MUFU.TANH + FMA
    float t;
    asm("tanh.approx.f32 %0, %1;" : "=f"(t) : "f"(0.5f * x));
    return fmaf(0.5f, t, 0.5f);
}

__global__ __launch_bounds__(THREADS)
void yolov7_head_kernel(const float* __restrict__ in,
                        const float* __restrict__ anchors,
                        float* __restrict__ out) {
    // output-linear layout: so[loc*85 + c]; quad-channel lane mapping makes
    // the scalar STS scatter fully bank-conflict-free.
    __shared__ __align__(16) float so[LOCS * YC];   // 21760 B

    const int blk   = blockIdx.x;
    const int chunk = blk % NCHUNK;
    const int ba    = blk / NCHUNK;       // b*A + a
    const int a     = ba % YA;
    const int hw0   = chunk * LOCS;

    const float aw = anchors[a * 2 + 0];
    const float ah = anchors[a * 2 + 1];

    const int tid  = threadIdx.x;
    const int warp = tid >> 5;
    const int lane = tid & 31;
    const int q    = lane >> 3;   // channel within quad (0..3)
    const int l8   = lane & 7;    // float4 within 8-block

    const float4* in4 = reinterpret_cast<const float4*>(
        in + (size_t)ba * YC * YHW + hw0);

    // ---- front-batched loads: all 6 LDG.128 issued before any use (MLP=6) ----
    float4 v[TPT];
    #pragma unroll
    for (int t = 0; t < TPT; t++) {
        const int task = warp + NWARP * t;
        const int c    = (task >> 1) * 4 + q;
        const int i4   = (task & 1) * 8 + l8;
        if (task < NTASKS && c < YC)
            v[t] = in4[c * (YHW / 4) + i4];
    }

    // ---- transform + conflict-free STS (output-linear scatter) ----
    #pragma unroll
    for (int t = 0; t < TPT; t++) {
        const int task = warp + NWARP * t;
        const int c    = (task >> 1) * 4 + q;
        const int i4   = (task & 1) * 8 + l8;
        if (task < NTASKS && c < YC) {
            const float vals[4] = {v[t].x, v[t].y, v[t].z, v[t].w};
            const int loc0 = i4 * 4;
            if (c >= 4) {
                #pragma unroll
                for (int k = 0; k < 4; k++)
                    so[(loc0 + k) * YC + c] = fast_sigmoid(vals[k]);
            } else if (c == 0) {
                #pragma unroll
                for (int k = 0; k < 4; k++) {
                    const int hw = hw0 + loc0 + k;
                    const float gx = (float)(hw % YW);
                    so[(loc0 + k) * YC + c] = (fast_sigmoid(vals[k]) + gx) * 8.0f;
                }
            } else if (c == 1) {
                #pragma unroll
                for (int k = 0; k < 4; k++) {
                    const int hw = hw0 + loc0 + k;
                    const float gy = (float)(hw / YW);
                    so[(loc0 + k) * YC + c] = (fast_sigmoid(vals[k]) + gy) * 8.0f;
                }
            } else {  // c == 2 or 3
                const float anc = (c == 2) ? aw : ah;
                #pragma unroll
                for (int k = 0; k < 4; k++) {
                    float x = fminf(fmaxf(vals[k], -16.0f), 16.0f);
                    so[(loc0 + k) * YC + c] = __expf(x) * anc;
                }
            }
        }
    }

    __syncthreads();

    // ---- single 1D TMA bulk store smem -> gmem ----
    if (tid == 0) {
        float* gdst = out + ((size_t)ba * YHW + hw0) * YC;
        uint32_t saddr;
        asm("{ .reg .u64 t; cvta.to.shared.u64 t, %1; cvt.u32.u64 %0, t; }"
            : "=r"(saddr) : "l"(so));
        asm volatile("fence.proxy.async.shared::cta;" ::: "memory");
        asm volatile(
            "cp.async.bulk.global.shared::cta.bulk_group [%0], [%1], %2;"
            :: "l"(gdst), "r"(saddr), "n"(TILE_BYTES) : "memory");
        asm volatile("cp.async.bulk.commit_group;" ::: "memory");
        // keep CTA (and its smem) alive until the bulk engine has read smem
        asm volatile("cp.async.bulk.wait_group.read 0;" ::: "memory");
    }
}

extern "C" void kernel_launch(void* const* d_in, const int* in_sizes, int n_in,
                              void* d_out, int out_size) {
    const float* in      = (const float*)d_in[0];
    const float* anchors = (const float*)d_in[1];
    float* out           = (float*)d_out;

    const int grid = YB * YA * NCHUNK;  // 4800
    yolov7_head_kernel<<<grid, THREADS>>>(in, anchors, out);
}

// round 9
// speedup vs baseline: 1.2530x; 1.0110x over previous
#include <cuda_runtime.h>
#include <cuda_bf16.h>
#include <cstdint>

// YOLOv7 P3 head: B=16, A=3, NC=80, H=W=80, stride=8.
// in : [B, A*85, H, W] fp32 (channel-major)
// out: [B, A*H*W, 85] fp32 (85 contiguous per location)

#define YB 16
#define YA 3
#define YC 85
#define YH 80
#define YW 80
#define YHW (YH * YW)        // 6400
#define LOCS 32              // spatial locations per tile
#define NCHUNK (YHW / LOCS)  // 200 tiles per (b,a)
#define THREADS 256
#define NWARP (THREADS / 32)

#define CGROUPS 22                   // ceil(85/4)
#define NTASKS CGROUPS               // 22 warp-tasks per tile (one 8x float4 block each)
#define TPT ((NTASKS + NWARP - 1) / NWARP)  // 3 tasks per thread

#define TILE_BYTES (LOCS * YC * 4)   // 10880

__device__ __forceinline__ float fast_sigmoid(float x) {
    // sigmoid(x) = 0.5*tanh(0.5x) + 0.5  -> single MUFU.TANH + FMA
    float t;
    asm("tanh.approx.f32 %0, %1;" : "=f"(t) : "f"(0.5f * x));
    return fmaf(0.5f, t, 0.5f);
}

__global__ __launch_bounds__(THREADS)
void yolov7_head_kernel(const float* __restrict__ in,
                        const float* __restrict__ anchors,
                        float* __restrict__ out) {
    // output-linear layout: so[loc*85 + c]; quad-channel lane mapping makes
    // the scalar STS scatter fully bank-conflict-free:
    // bank = (20*l8 + q) mod 32 -> all 32 lanes distinct.
    __shared__ __align__(16) float so[LOCS * YC];   // 10880 B

    const int blk   = blockIdx.x;
    const int chunk = blk % NCHUNK;
    const int ba    = blk / NCHUNK;       // b*A + a
    const int a     = ba % YA;
    const int hw0   = chunk * LOCS;

    const float aw = anchors[a * 2 + 0];
    const float ah = anchors[a * 2 + 1];

    const int tid  = threadIdx.x;
    const int warp = tid >> 5;
    const int lane = tid & 31;
    const int q    = lane >> 3;   // channel within quad (0..3)
    const int l8   = lane & 7;    // float4 index (0..7) -> loc0 = 4*l8

    const float4* in4 = reinterpret_cast<const float4*>(
        in + (size_t)ba * YC * YHW + hw0);

    // ---- front-batched loads: all 3 LDG.128 issued before any use ----
    float4 v[TPT];
    #pragma unroll
    for (int t = 0; t < TPT; t++) {
        const int task = warp + NWARP * t;    // channel-quad index
        const int c    = task * 4 + q;
        if (task < NTASKS && c < YC)
            v[t] = in4[c * (YHW / 4) + l8];
    }

    // ---- transform + conflict-free STS (output-linear scatter) ----
    #pragma unroll
    for (int t = 0; t < TPT; t++) {
        const int task = warp + NWARP * t;
        const int c    = task * 4 + q;
        if (task < NTASKS && c < YC) {
            const float vals[4] = {v[t].x, v[t].y, v[t].z, v[t].w};
            const int loc0 = l8 * 4;
            if (c >= 4) {
                #pragma unroll
                for (int k = 0; k < 4; k++)
                    so[(loc0 + k) * YC + c] = fast_sigmoid(vals[k]);
            } else if (c == 0) {
                #pragma unroll
                for (int k = 0; k < 4; k++) {
                    const int hw = hw0 + loc0 + k;
                    const float gx = (float)(hw % YW);
                    so[(loc0 + k) * YC + c] = (fast_sigmoid(vals[k]) + gx) * 8.0f;
                }
            } else if (c == 1) {
                #pragma unroll
                for (int k = 0; k < 4; k++) {
                    const int hw = hw0 + loc0 + k;
                    const float gy = (float)(hw / YW);
                    so[(loc0 + k) * YC + c] = (fast_sigmoid(vals[k]) + gy) * 8.0f;
                }
            } else {  // c == 2 or 3
                const float anc = (c == 2) ? aw : ah;
                #pragma unroll
                for (int k = 0; k < 4; k++) {
                    float x = fminf(fmaxf(vals[k], -16.0f), 16.0f);
                    so[(loc0 + k) * YC + c] = __expf(x) * anc;
                }
            }
        }
    }

    __syncthreads();

    // ---- single 1D TMA bulk store smem -> gmem ----
    if (tid == 0) {
        float* gdst = out + ((size_t)ba * YHW + hw0) * YC;
        uint32_t saddr;
        asm("{ .reg .u64 t; cvta.to.shared.u64 t, %1; cvt.u32.u64 %0, t; }"
            : "=r"(saddr) : "l"(so));
        asm volatile("fence.proxy.async.shared::cta;" ::: "memory");
        asm volatile(
            "cp.async.bulk.global.shared::cta.bulk_group [%0], [%1], %2;"
            :: "l"(gdst), "r"(saddr), "n"(TILE_BYTES) : "memory");
        asm volatile("cp.async.bulk.commit_group;" ::: "memory");
        // keep CTA (and its smem) alive until the bulk engine has read smem
        asm volatile("cp.async.bulk.wait_group.read 0;" ::: "memory");
    }
}

extern "C" void kernel_launch(void* const* d_in, const int* in_sizes, int n_in,
                              void* d_out, int out_size) {
    const float* in      = (const float*)d_in[0];
    const float* anchors = (const float*)d_in[1];
    float* out           = (float*)d_out;

    const int grid = YB * YA * NCHUNK;  // 9600
    yolov7_head_kernel<<<grid, THREADS>>>(in, anchors, out);
}